// round 17
// baseline (speedup 1.0000x reference)
#include <cuda_runtime.h>
#include <cuda_bf16.h>
#include <cstdint>

#define NB_BATCH 16
#define NB_NH    32
#define NB_KVH   8
#define NB_NREP  4
#define NB_HD    128
#define NB_SCALE 0.08838834764831845f
#define NB_BPS   256
#define NB_NSPLIT 16
#define NB_CHUNK  256

// split-KV partial scratch (device globals: allocation-free)
__device__ float g_pacc[NB_BATCH * NB_KVH * NB_NSPLIT * NB_NREP * NB_HD]; // 4 MB
__device__ float g_pm[NB_BATCH * NB_KVH * NB_NSPLIT * NB_NREP];
__device__ float g_pl[NB_BATCH * NB_KVH * NB_NSPLIT * NB_NREP];
__device__ int   g_cnt[NB_BATCH * NB_KVH];   // zero-init; reset by reducer CTA

// packed f32x2 dot: (q.x*k.x+q.z*k.z) + (q.y*k.y+q.w*k.w)  [FFMA2 path]
__device__ __forceinline__ float dot4_p(const float4 qv, const float4 kv) {
    float lo, hi;
    asm("{\n\t"
        ".reg .b64 qa,qb,ka,kb,t,r;\n\t"
        "mov.b64 qa, {%2,%3};\n\t"
        "mov.b64 qb, {%4,%5};\n\t"
        "mov.b64 ka, {%6,%7};\n\t"
        "mov.b64 kb, {%8,%9};\n\t"
        "mul.rn.f32x2 t, qb, kb;\n\t"
        "fma.rn.f32x2 r, qa, ka, t;\n\t"
        "mov.b64 {%0,%1}, r;\n\t"
        "}"
        : "=f"(lo), "=f"(hi)
        : "f"(qv.x), "f"(qv.y), "f"(qv.z), "f"(qv.w),
          "f"(kv.x), "f"(kv.y), "f"(kv.z), "f"(kv.w));
    return lo + hi;
}

// packed f32x2 acc: a += p * v (4 wide, 2x FFMA2)
__device__ __forceinline__ void fma4_p(float4& a, const float p, const float4 vv) {
    asm("{\n\t"
        ".reg .b64 pp,v01,v23,a01,a23;\n\t"
        "mov.b64 pp,  {%4,%4};\n\t"
        "mov.b64 v01, {%5,%6};\n\t"
        "mov.b64 v23, {%7,%8};\n\t"
        "mov.b64 a01, {%0,%1};\n\t"
        "mov.b64 a23, {%2,%3};\n\t"
        "fma.rn.f32x2 a01, pp, v01, a01;\n\t"
        "fma.rn.f32x2 a23, pp, v23, a23;\n\t"
        "mov.b64 {%0,%1}, a01;\n\t"
        "mov.b64 {%2,%3}, a23;\n\t"
        "}"
        : "+f"(a.x), "+f"(a.y), "+f"(a.z), "+f"(a.w)
        : "f"(p), "f"(vv.x), "f"(vv.y), "f"(vv.z), "f"(vv.w));
}

__device__ __forceinline__ void cp_async16(uint32_t dst, const float* src) {
    asm volatile("cp.async.cg.shared.global [%0], [%1], 16;" :: "r"(dst), "l"(src) : "memory");
}
#define CP_COMMIT()  asm volatile("cp.async.commit_group;" ::: "memory")
#define CP_WAIT(N)   asm volatile("cp.async.wait_group %0;" :: "n"(N) : "memory")

#define NB_SLOTS 5   // smem ring slots
#define NB_TPS   2   // token-iters per stage per warp

__global__ __launch_bounds__(256, 4) void attn_split(
    const float* __restrict__ q,
    const float* __restrict__ kn,
    const float* __restrict__ vn,
    const float* __restrict__ kc,
    const float* __restrict__ vc,
    const int* __restrict__ bt,
    const int* __restrict__ ctx,
    const int* __restrict__ slotmap,
    float* __restrict__ out)
{
    const int split = blockIdx.x, g = blockIdx.y, b = blockIdx.z;
    const int bg = b * NB_KVH + g;
    const int cl = ctx[b];
    const int j0 = split * NB_CHUNK;
    const bool active = (j0 < cl);

    // ring: [slot][w*NB_TPS+j][lane] — each lane cp.async's and reads its OWN 16B
    __shared__ __align__(16) union {
        float4 ring[NB_SLOTS][8 * NB_TPS][32];    // 40 KB
        float  wacc[8][NB_NREP][NB_HD];           // 16 KB, used after streams drain
    } u;
    __shared__ int   sbt[16];
    __shared__ int   sslot[16];
    __shared__ int   stok[NB_CHUNK];     // enc: ov>=0 ? ~ov : cache-slot
    __shared__ float4 sp[NB_CHUNK];
    __shared__ float wred[8][4];
    __shared__ float smx[4];
    __shared__ int   s_old;
    __shared__ float rM[4], rL[4], rE[4][NB_NSPLIT];

    const int tid = threadIdx.x;
    const int w = tid >> 5, lane = tid & 31;

    if (active) {
        const int vcnt = min(NB_CHUNK, cl - j0);

        if (tid < 16) {
            sbt[tid]   = bt[b * NB_BPS + split * 16 + tid];
            sslot[tid] = slotmap[tid];
        }
        __syncthreads();
        {   // per-token source encoding — valid for ALL 256 t regardless of vcnt
            const int t = tid;
            const int sl = sbt[t >> 4] * 16 + (t & 15);
            int ov = -1;
            #pragma unroll
            for (int bp = 0; bp < NB_BATCH; bp++)
                if (sslot[bp] == sl) ov = bp;     // last match wins
            stok[t] = (ov >= 0) ? ~ov : sl;
        }
        __syncthreads();

        // padded trip count (multiple of 4) -> stages of NB_TPS token-iters
        const int nt4 = (((vcnt + 7) >> 3) + 3) & ~3;
        const int nstg = nt4 >> 1;               // >=2, even, <=16

        const float* kc_g = kc + g * NB_HD;
        const float* kn_g = kn + g * NB_HD;
        const float* vc_g = vc + g * NB_HD;
        const float* vn_g = vn + g * NB_HD;

        // stage issue: 2 tokens for this warp, one commit group
        auto issue = [&](int c, const float* bc, const float* bn) {
            const int st = c % nstg;
            const int slot = c % NB_SLOTS;
            #pragma unroll
            for (int j = 0; j < NB_TPS; j++) {
                const int t = (st * NB_TPS + j) * 8 + w;
                const int e = stok[t];
                const int row = (e < 0) ? ~e : e;
                const float* base = (e < 0) ? bn : bc;
                const float* src = base + (size_t)row * (NB_KVH * NB_HD) + lane * 4;
                cp_async16((uint32_t)__cvta_generic_to_shared(
                               &u.ring[slot][w * NB_TPS + j][lane]), src);
            }
            CP_COMMIT();
        };

        // ---- Pass 1: scores (K stream), 4-deep cp.async pipeline ----
        {
            const float* qb = q + ((size_t)b * NB_NH + g * NB_NREP) * NB_HD + lane * 4;
            float4 q0 = *(const float4*)(qb + 0 * NB_HD);
            float4 q1 = *(const float4*)(qb + 1 * NB_HD);
            float4 q2 = *(const float4*)(qb + 2 * NB_HD);
            float4 q3 = *(const float4*)(qb + 3 * NB_HD);
            q0.x *= NB_SCALE; q0.y *= NB_SCALE; q0.z *= NB_SCALE; q0.w *= NB_SCALE;
            q1.x *= NB_SCALE; q1.y *= NB_SCALE; q1.z *= NB_SCALE; q1.w *= NB_SCALE;
            q2.x *= NB_SCALE; q2.y *= NB_SCALE; q2.z *= NB_SCALE; q2.w *= NB_SCALE;
            q3.x *= NB_SCALE; q3.y *= NB_SCALE; q3.z *= NB_SCALE; q3.w *= NB_SCALE;
            const bool b0 = (lane & 1) != 0;
            const bool b1 = (lane & 2) != 0;
            const int hm = ((lane & 1) << 1) | ((lane >> 1) & 1);

            issue(0, kc_g, kn_g); issue(1, kc_g, kn_g);
            issue(2, kc_g, kn_g); issue(3, kc_g, kn_g);

            #pragma unroll 1
            for (int s = 0; s < nstg; s++) {
                CP_WAIT(3);                       // stage s landed
                const int slot = s % NB_SLOTS;
                #pragma unroll
                for (int j = 0; j < NB_TPS; j++) {
                    const int t = (s * NB_TPS + j) * 8 + w;
                    const float4 kk = u.ring[slot][w * NB_TPS + j][lane];
                    float s0 = dot4_p(q0, kk);
                    float s1 = dot4_p(q1, kk);
                    float s2 = dot4_p(q2, kk);
                    float s3 = dot4_p(q3, kk);
                    float uu = b0 ? s0 : s2;
                    float vS = b0 ? s1 : s3;
                    float ru = __shfl_xor_sync(0xffffffffu, uu, 1);
                    float rv = __shfl_xor_sync(0xffffffffu, vS, 1);
                    float a0 = (b0 ? s2 : s0) + ru;
                    float a1 = (b0 ? s3 : s1) + rv;
                    float ub = b1 ? a0 : a1;
                    float rb = __shfl_xor_sync(0xffffffffu, ub, 2);
                    float bb = (b1 ? a1 : a0) + rb;
                    bb += __shfl_xor_sync(0xffffffffu, bb, 4);
                    bb += __shfl_xor_sync(0xffffffffu, bb, 8);
                    bb += __shfl_xor_sync(0xffffffffu, bb, 16);
                    if (lane < 4) ((float*)&sp[t])[hm] = bb;
                }
                issue(s + 4, kc_g, kn_g);
            }
            CP_WAIT(0);
        }
        __syncthreads();

        // ---- Block softmax over the chunk ----
        {
            const int t = tid;
            float4 s4 = sp[t];
            if (t >= vcnt) { s4.x = s4.y = s4.z = s4.w = -1e30f; }
            float m0 = s4.x, m1 = s4.y, m2 = s4.z, m3 = s4.w;
            #pragma unroll
            for (int off = 16; off >= 1; off >>= 1) {
                m0 = fmaxf(m0, __shfl_xor_sync(0xffffffffu, m0, off));
                m1 = fmaxf(m1, __shfl_xor_sync(0xffffffffu, m1, off));
                m2 = fmaxf(m2, __shfl_xor_sync(0xffffffffu, m2, off));
                m3 = fmaxf(m3, __shfl_xor_sync(0xffffffffu, m3, off));
            }
            if (lane == 0) { wred[w][0] = m0; wred[w][1] = m1; wred[w][2] = m2; wred[w][3] = m3; }
            __syncthreads();
            if (tid < 4) {
                float mm = wred[0][tid];
                #pragma unroll
                for (int ww = 1; ww < 8; ww++) mm = fmaxf(mm, wred[ww][tid]);
                smx[tid] = mm;
            }
            __syncthreads();
            const float M0 = smx[0], M1 = smx[1], M2 = smx[2], M3 = smx[3];
            float e0 = 0.f, e1 = 0.f, e2 = 0.f, e3 = 0.f;
            if (t < vcnt) {
                e0 = __expf(s4.x - M0); e1 = __expf(s4.y - M1);
                e2 = __expf(s4.z - M2); e3 = __expf(s4.w - M3);
            }
            sp[t] = make_float4(e0, e1, e2, e3);
            #pragma unroll
            for (int off = 16; off >= 1; off >>= 1) {
                e0 += __shfl_xor_sync(0xffffffffu, e0, off);
                e1 += __shfl_xor_sync(0xffffffffu, e1, off);
                e2 += __shfl_xor_sync(0xffffffffu, e2, off);
                e3 += __shfl_xor_sync(0xffffffffu, e3, off);
            }
            if (lane == 0) { wred[w][0] = e0; wred[w][1] = e1; wred[w][2] = e2; wred[w][3] = e3; }
            __syncthreads();
            if (tid < 4) {
                float ss = wred[0][tid];
                #pragma unroll
                for (int ww = 1; ww < 8; ww++) ss += wred[ww][tid];
                const size_t pidx = ((size_t)bg * NB_NSPLIT + split) * NB_NREP + tid;
                g_pm[pidx] = smx[tid];
                g_pl[pidx] = ss;
            }
            __syncthreads();
        }

        // ---- Pass 2: output accumulation (V stream), 4-deep pipeline ----
        {
            float4 a0 = make_float4(0.f,0.f,0.f,0.f), a1 = a0, a2 = a0, a3 = a0;

            issue(0, vc_g, vn_g); issue(1, vc_g, vn_g);
            issue(2, vc_g, vn_g); issue(3, vc_g, vn_g);

            #pragma unroll 1
            for (int s = 0; s < nstg; s++) {
                CP_WAIT(3);
                const int slot = s % NB_SLOTS;
                #pragma unroll
                for (int j = 0; j < NB_TPS; j++) {
                    const int t = (s * NB_TPS + j) * 8 + w;
                    const float4 vv = u.ring[slot][w * NB_TPS + j][lane];
                    const float4 p = sp[t];
                    fma4_p(a0, p.x, vv); fma4_p(a1, p.y, vv);
                    fma4_p(a2, p.z, vv); fma4_p(a3, p.w, vv);
                }
                issue(s + 4, vc_g, vn_g);
            }
            CP_WAIT(0);          // this thread's copies drained
            __syncthreads();     // ALL threads drained -> ring reusable as wacc

            *(float4*)&u.wacc[w][0][lane * 4] = a0;
            *(float4*)&u.wacc[w][1][lane * 4] = a1;
            *(float4*)&u.wacc[w][2][lane * 4] = a2;
            *(float4*)&u.wacc[w][3][lane * 4] = a3;
        }
        __syncthreads();

        // combine the 8 warps' partials and store (unnormalized)
        {
            const size_t pbase = ((size_t)bg * NB_NSPLIT + split) * NB_NREP;
            #pragma unroll
            for (int o = tid; o < NB_NREP * NB_HD; o += 256) {
                const int h = o >> 7, d = o & 127;
                float s = u.wacc[0][h][d];
                #pragma unroll
                for (int ww = 1; ww < 8; ww++) s += u.wacc[ww][h][d];
                g_pacc[(pbase + h) * NB_HD + d] = s;
            }
        }
        __threadfence();
    }
    __syncthreads();

    // ---- arrival + last-CTA-done reduction for this (b,g) ----
    if (tid == 0) s_old = atomicAdd(&g_cnt[bg], 1);
    __syncthreads();
    if (s_old != NB_NSPLIT - 1) return;

    __threadfence();   // acquire: observe all 16 CTAs' partials
    const int ns = min(NB_NSPLIT, (cl + NB_CHUNK - 1) >> 8);
    const size_t base = (size_t)bg * NB_NSPLIT * NB_NREP;

    if (tid < 4) {
        float M = -1e30f;
        for (int s = 0; s < ns; s++)
            M = fmaxf(M, g_pm[base + (size_t)s * NB_NREP + tid]);
        rM[tid] = M;
    }
    __syncthreads();
    if (tid < 64) {
        const int h = tid & 3, s = tid >> 2;
        rE[h][s] = (s < ns) ? __expf(g_pm[base + (size_t)s * NB_NREP + h] - rM[h]) : 0.f;
    }
    __syncthreads();
    if (tid < 4) {
        float L = 0.f;
        #pragma unroll
        for (int s = 0; s < NB_NSPLIT; s++)   // stale g_pl * e==0 contributes 0
            L = fmaf(g_pl[base + (size_t)s * NB_NREP + tid], rE[tid][s], L);
        rL[tid] = L;
    }
    __syncthreads();
    if (tid < 128) {
        const int h = tid >> 5, c = tid & 31;
        float4 o = make_float4(0.f, 0.f, 0.f, 0.f);
        #pragma unroll
        for (int s = 0; s < NB_NSPLIT; s++) { // stale g_pacc * e==0 contributes 0
            const float e = rE[h][s];
            const float4 a = *(const float4*)(g_pacc + (base + (size_t)s * NB_NREP + h) * NB_HD + c * 4);
            fma4_p(o, e, a);
        }
        const float inv = 1.f / rL[h];
        const size_t ob = ((size_t)(b * NB_NH + g * NB_NREP + h)) * NB_HD + c * 4;
        *(float4*)(out + ob) = make_float4(o.x * inv, o.y * inv, o.z * inv, o.w * inv);
    }
    if (tid == 0) g_cnt[bg] = 0;   // reset for next (graph) launch
}

extern "C" void kernel_launch(void* const* d_in, const int* in_sizes, int n_in,
                              void* d_out, int out_size)
{
    const float* q    = (const float*)d_in[0];
    const float* k    = (const float*)d_in[1];
    const float* v    = (const float*)d_in[2];
    const float* kc   = (const float*)d_in[3];
    const float* vc   = (const float*)d_in[4];
    const int*   bt   = (const int*)d_in[5];
    const int*   ctx  = (const int*)d_in[6];
    const int*   slot = (const int*)d_in[7];

    dim3 grid(NB_NSPLIT, NB_KVH, NB_BATCH);
    attn_split<<<grid, 256>>>(q, k, v, kc, vc, bt, ctx, slot, (float*)d_out);
}